// round 5
// baseline (speedup 1.0000x reference)
#include <cuda_runtime.h>
#include <cuda_fp16.h>
#include <math.h>
#include <stdint.h>

#define B_ 32
#define T_ 8
#define K_ 64
#define D_ 512
#define CIN_ 1536
#define HW_ 64
#define NT_ 256

// ---------------- scratch (device globals; no allocation) ----------------
__device__ float g_xt [NT_ * D_ * HW_];   // (n, d, s)
__device__ float g_xtT[NT_ * HW_ * D_];   // (n, s, d)
__device__ __half g_xh[(size_t)NT_ * HW_ * CIN_]; // (col, cin) K-major fp16
__device__ __half g_wh[640 * CIN_];       // rows 0-511: W; 512-575: wx@W; 576-639: 0
__device__ float g_biasx[640];            // 0-511: redu_b; 512-575: wx@redu_b; pad 0
__device__ float g_wxpb[NT_ * K_ * HW_];
__device__ float g_attv[NT_ * K_ * HW_];
__device__ float g_hs [T_ * B_ * K_ * HW_];
__device__ float g_h   [B_ * K_ * HW_];
__device__ float g_ah  [B_ * K_ * HW_];
__device__ float g_uz  [B_ * K_ * HW_];
__device__ float g_ur  [B_ * K_ * HW_];
__device__ float g_wxt0[B_ * K_ * HW_];
__device__ float g_wxtb[B_ * K_ * HW_];
__device__ float g_zb  [B_ * K_ * HW_];
__device__ float g_rh  [B_ * K_ * HW_];
__device__ float g_vlad[B_ * K_ * D_];

__device__ __forceinline__ float sigmoidf_(float x) { return 1.f / (1.f + expf(-x)); }
__device__ __forceinline__ uint32_t smem_to_u32(const void* p) {
    uint32_t a;
    asm("{ .reg .u64 t; cvta.to.shared.u64 t, %1; cvt.u32.u64 %0, t; }"
        : "=r"(a) : "l"(p));
    return a;
}

// ---------------- convert W to fp16 (rows 0-511) + zero pad rows 576-639 ----
__global__ void convert_w(const float* __restrict__ W) {
    int i = blockIdx.x * 1024 + threadIdx.x;
    if (i >= 640 * CIN_) return;
    int d = i / CIN_;
    if (d < 512) g_wh[i] = __float2half(W[i]);
    else if (d >= 576) g_wh[i] = __float2half(0.f);
}

// ---------------- wxW = w_x @ W (fp16 rows 512-575) + bias vector ----------
__global__ void __launch_bounds__(256) wxw_kernel(const float* __restrict__ redu_w,
                                                  const float* __restrict__ redu_b,
                                                  const float* __restrict__ wx) {
    __shared__ float sW[128 * 16];    // W chunk [128 d][16 c]
    __shared__ float sX[64 * 128];    // wx chunk [64 k][128 d]
    int tid = threadIdx.x;
    int c0 = blockIdx.x * 16;
    int c_l = tid & 15, kq = tid >> 4;   // 16 k-groups of 4
    float acc[4] = {0.f, 0.f, 0.f, 0.f};
    for (int dc = 0; dc < 4; dc++) {
        __syncthreads();
        for (int i = tid; i < 2048; i += 256) {
            int dd = i >> 4, c = i & 15;
            sW[i] = redu_w[(size_t)(dc * 128 + dd) * CIN_ + c0 + c];
        }
        for (int i = tid; i < 8192; i += 256) {
            int k = i >> 7, dd = i & 127;
            sX[i] = wx[k * 512 + dc * 128 + dd];
        }
        __syncthreads();
        for (int dd = 0; dd < 128; dd++) {
            float wv = sW[dd * 16 + c_l];
#pragma unroll
            for (int i = 0; i < 4; i++)
                acc[i] += sX[(kq * 4 + i) * 128 + dd] * wv;
        }
    }
#pragma unroll
    for (int i = 0; i < 4; i++)
        g_wh[(size_t)(512 + kq * 4 + i) * CIN_ + c0 + c_l] = __float2half(acc[i]);

    if (blockIdx.x == 0) {
        if (tid < 256) {
            g_biasx[tid] = redu_b[tid];
            g_biasx[tid + 256] = redu_b[tid + 256];
        }
        if (tid < 64) {
            float s = 0.f;
            for (int d = 0; d < 512; d++) s += wx[tid * 512 + d] * redu_b[d];
            g_biasx[512 + tid] = s;
            g_biasx[576 + tid] = 0.f;
        }
    }
}

// ---------------- transpose x (n,cin,s) fp32 -> xh[(n*64+s)][cin] fp16 -------
__global__ void __launch_bounds__(256) transpose_x(const float* __restrict__ x) {
    __shared__ float sm[64 * 65];
    int n = blockIdx.y, c0 = blockIdx.x * 64;
    const float* src = x + ((size_t)n * CIN_ + c0) * 64;
    for (int i = threadIdx.x; i < 4096; i += 256) {
        int ci = i >> 6, s = i & 63;
        sm[ci * 65 + s] = src[i];
    }
    __syncthreads();
#pragma unroll
    for (int rep = 0; rep < 8; rep++) {
        int idx = rep * 256 + threadIdx.x;
        int s = idx >> 5, cp = idx & 31, ci = cp * 2;
        __half2 h = __floats2half2_rn(sm[ci * 65 + s], sm[(ci + 1) * 65 + s]);
        *(__half2*)(g_xh + ((size_t)(n * 64 + s)) * CIN_ + c0 + ci) = h;
    }
}

// ============== HMMA GEMM, 3-stage cp.async pipeline ========================
#define GPAD 40
#define EPAD 67
#define NCH 48
#define STG 20480             // bytes per stage (A 10240 + B 10240)
#define GSMEM (3 * STG)       // 61440 >= 128*EPAD*4 epilogue

__device__ __forceinline__ void mma16816(float* c, const uint32_t* a, const uint32_t* b) {
    asm volatile(
        "mma.sync.aligned.m16n8k16.row.col.f32.f16.f16.f32 "
        "{%0,%1,%2,%3}, {%4,%5,%6,%7}, {%8,%9}, {%0,%1,%2,%3};"
        : "+f"(c[0]), "+f"(c[1]), "+f"(c[2]), "+f"(c[3])
        : "r"(a[0]), "r"(a[1]), "r"(a[2]), "r"(a[3]), "r"(b[0]), "r"(b[1]));
}
#define LDSM4(r0, r1, r2, r3, addr) \
    asm volatile("ldmatrix.sync.aligned.m8n8.x4.shared.b16 {%0,%1,%2,%3}, [%4];" \
                 : "=r"(r0), "=r"(r1), "=r"(r2), "=r"(r3) : "r"(addr))
#define CPASYNC16(saddr, gptr) \
    asm volatile("cp.async.cg.shared.global [%0], [%1], 16;" :: "r"(saddr), "l"(gptr))
#define CPCOMMIT() asm volatile("cp.async.commit_group;")
#define CPWAIT(n)  asm volatile("cp.async.wait_group %0;" :: "n"(n))

__global__ void __launch_bounds__(256) gemm_redu_mma() {
    extern __shared__ __align__(16) char sbuf[];
    float* sEp = (float*)sbuf;
    uint32_t sb = smem_to_u32(sbuf);

    int tid = threadIdx.x;
    int wid = tid >> 5, lane = tid & 31;
    int warp_m = wid >> 2, warp_n = wid & 3;
    int moff = warp_m * 64, noff = warp_n * 32;
    int m0 = blockIdx.x * 128, n0 = blockIdx.y * 128;
    int lr = lane >> 2, lc = (lane & 3) * 2;

    float acc[4][4][4];
#pragma unroll
    for (int i = 0; i < 4; i++)
#pragma unroll
        for (int j = 0; j < 4; j++)
#pragma unroll
            for (int q = 0; q < 4; q++) acc[i][j][q] = 0.f;

    int lane16 = lane & 15, lanehi = lane >> 4;
    uint32_t aBase = sb + (uint32_t)((moff + lane16) * 80 + lanehi * 16);
    int bgrp = lane >> 3;
    int brow = (lane & 7) + ((bgrp >> 1) << 3);
    int bcol = (bgrp & 1) << 3;
    uint32_t bBase = sb + 10240 + (uint32_t)((noff + brow) * 80 + bcol * 2);

    auto load_chunk = [&](int st, int ch) {
        int k0 = ch * 32;
        uint32_t abuf = sb + st * STG, bbuf = abuf + 10240;
#pragma unroll
        for (int i = tid; i < 512; i += 256) {
            int r = i >> 2, c = i & 3;
            CPASYNC16(abuf + (uint32_t)(r * 80 + c * 16),
                      g_xh + (size_t)(m0 + r) * CIN_ + k0 + c * 8);
            CPASYNC16(bbuf + (uint32_t)(r * 80 + c * 16),
                      g_wh + (size_t)(n0 + r) * CIN_ + k0 + c * 8);
        }
    };

    load_chunk(0, 0);
    CPCOMMIT();
    load_chunk(1, 1);
    CPCOMMIT();

#pragma unroll 1
    for (int ch = 0; ch < NCH; ch++) {
        if (ch < NCH - 1) CPWAIT(1); else CPWAIT(0);
        __syncthreads();
        if (ch + 2 < NCH) {
            load_chunk((ch + 2) % 3, ch + 2);
            CPCOMMIT();
        }
        uint32_t stoff = (uint32_t)((ch % 3) * STG);
        uint32_t af[2][4][4], bf[2][4][2];
#pragma unroll
        for (int ks = 0; ks < 2; ks++) {
#pragma unroll
            for (int mf = 0; mf < 4; mf++)
                LDSM4(af[ks][mf][0], af[ks][mf][1], af[ks][mf][2], af[ks][mf][3],
                      aBase + stoff + (uint32_t)(mf * 16 * 80 + ks * 32));
#pragma unroll
            for (int nfp = 0; nfp < 2; nfp++)
                LDSM4(bf[ks][2 * nfp][0], bf[ks][2 * nfp][1],
                      bf[ks][2 * nfp + 1][0], bf[ks][2 * nfp + 1][1],
                      bBase + stoff + (uint32_t)(nfp * 16 * 80 + ks * 32));
        }
#pragma unroll
        for (int ks = 0; ks < 2; ks++)
#pragma unroll
            for (int mf = 0; mf < 4; mf++)
#pragma unroll
                for (int nf = 0; nf < 4; nf++)
                    mma16816(acc[mf][nf], af[ks][mf], bf[ks][nf]);
    }

    if (n0 < 512) {
        // xt / xtT epilogue, two 64-d slabs
#pragma unroll 1
        for (int slab = 0; slab < 2; slab++) {
            __syncthreads();
            if ((warp_n >> 1) == slab) {
                int ncol = (warp_n & 1) * 32;
#pragma unroll
                for (int mf = 0; mf < 4; mf++) {
                    int row = moff + mf * 16 + lr;
#pragma unroll
                    for (int nf = 0; nf < 4; nf++) {
                        int col = ncol + nf * 8 + lc;
                        sEp[row * EPAD + col]           = acc[mf][nf][0];
                        sEp[row * EPAD + col + 1]       = acc[mf][nf][1];
                        sEp[(row + 8) * EPAD + col]     = acc[mf][nf][2];
                        sEp[(row + 8) * EPAD + col + 1] = acc[mf][nf][3];
                    }
                }
            }
            __syncthreads();
            int dbase = n0 + slab * 64;
#pragma unroll
            for (int idx = tid; idx < 8192; idx += 256) {
                int m = idx & 127, dn = idx >> 7;
                int col = m0 + m, nn = col >> 6, ss = col & 63;
                int d = dbase + dn;
                g_xt[(size_t)nn * (D_ * HW_) + d * 64 + ss] = sEp[m * EPAD + dn] + g_biasx[d];
            }
#pragma unroll
            for (int idx = tid; idx < 8192; idx += 256) {
                int dn = idx & 63, m = idx >> 6;
                int col = m0 + m, nn = col >> 6, ss = col & 63;
                int d = dbase + dn;
                g_xtT[(size_t)nn * (HW_ * D_) + ss * 512 + d] = sEp[m * EPAD + dn] + g_biasx[d];
            }
        }
    } else {
        // wxpb epilogue (valid rows: k = 0..63 -> slab 0 only)
        __syncthreads();
        if ((warp_n >> 1) == 0) {
            int ncol = (warp_n & 1) * 32;
#pragma unroll
            for (int mf = 0; mf < 4; mf++) {
                int row = moff + mf * 16 + lr;
#pragma unroll
                for (int nf = 0; nf < 4; nf++) {
                    int col = ncol + nf * 8 + lc;
                    sEp[row * EPAD + col]           = acc[mf][nf][0];
                    sEp[row * EPAD + col + 1]       = acc[mf][nf][1];
                    sEp[(row + 8) * EPAD + col]     = acc[mf][nf][2];
                    sEp[(row + 8) * EPAD + col + 1] = acc[mf][nf][3];
                }
            }
        }
        __syncthreads();
#pragma unroll
        for (int idx = tid; idx < 8192; idx += 256) {
            int m = idx & 127, dn = idx >> 7;   // dn = k (0..63)
            int col = m0 + m, nn = col >> 6, ss = col & 63;
            g_wxpb[nn * 4096 + dn * 64 + ss] = sEp[m * EPAD + dn] + g_biasx[512 + dn];
        }
    }
}

// ============== conv3x3 v2: block = (image, 16-outch group), 128 threads ======
#define CPAD 96
#define WPAD 292

__device__ __forceinline__ void conv3x3_v2(const float* __restrict__ gin,
                                           const float* __restrict__ gw, int oc0,
                                           float* sIn, float* sW, float acc[8]) {
    int tid = threadIdx.x;
    int y = tid & 7;
    int oc_l = tid >> 3;
    for (int i = tid; i < 4096; i += 128) {
        int ic = i >> 6, yy = (i >> 3) & 7, xx = i & 7;
        sIn[ic * CPAD + yy * 12 + xx] = gin[i];
    }
#pragma unroll
    for (int j = 0; j < 8; j++) acc[j] = 0.f;

#pragma unroll 1
    for (int half = 0; half < 2; half++) {
        __syncthreads();
        for (int i = tid; i < 4608; i += 128) {
            int oc = i / 288, icq = i - oc * 288;
            sW[oc * WPAD + icq] = gw[(oc0 + oc) * 576 + half * 288 + icq];
        }
        __syncthreads();
        const float* wrow = sW + oc_l * WPAD;
#pragma unroll 2
        for (int ic = 0; ic < 32; ic++) {
            const float* ip = sIn + (half * 32 + ic) * CPAD;
            float f[3][8];
#pragma unroll
            for (int r = 0; r < 3; r++) {
                int yy = y + r - 1;
                if (yy >= 0 && yy < 8) {
                    float4 v0 = *(const float4*)(ip + yy * 12);
                    float4 v1 = *(const float4*)(ip + yy * 12 + 4);
                    f[r][0] = v0.x; f[r][1] = v0.y; f[r][2] = v0.z; f[r][3] = v0.w;
                    f[r][4] = v1.x; f[r][5] = v1.y; f[r][6] = v1.z; f[r][7] = v1.w;
                } else {
#pragma unroll
                    for (int q = 0; q < 8; q++) f[r][q] = 0.f;
                }
            }
            const float* wp = wrow + ic * 9;
#pragma unroll
            for (int r = 0; r < 3; r++) {
                float w0 = wp[r * 3], w1 = wp[r * 3 + 1], w2 = wp[r * 3 + 2];
                acc[0] += w1 * f[r][0] + w2 * f[r][1];
#pragma unroll
                for (int j = 1; j < 7; j++)
                    acc[j] += w0 * f[r][j - 1] + w1 * f[r][j] + w2 * f[r][j + 1];
                acc[7] += w0 * f[r][6] + w1 * f[r][7];
            }
        }
    }
}

__global__ void __launch_bounds__(128) conv_plain_v2(const float* __restrict__ in,
                                                     const float* __restrict__ w,
                                                     float* __restrict__ out) {
    __shared__ float sIn[64 * CPAD];
    __shared__ float sW[16 * WPAD];
    int n = blockIdx.x, oc0 = blockIdx.y * 16;
    float acc[8];
    conv3x3_v2(in + n * 4096, w, oc0, sIn, sW, acc);
    int y = threadIdx.x & 7, oc = oc0 + (threadIdx.x >> 3);
    float* o = out + n * 4096 + oc * 64 + y * 8;
#pragma unroll
    for (int j = 0; j < 8; j++) o[j] = acc[j];
}

__global__ void __launch_bounds__(128) conv_trio_v2(const float* __restrict__ w_ah,
                                                    const float* __restrict__ b_ah,
                                                    const float* __restrict__ w_uz,
                                                    const float* __restrict__ w_ur) {
    __shared__ float sIn[64 * CPAD];
    __shared__ float sW[16 * WPAD];
    int n = blockIdx.x, which = blockIdx.y, oc0 = blockIdx.z * 16;
    const float* w = (which == 0) ? w_ah : (which == 1) ? w_uz : w_ur;
    float* out = (which == 0) ? g_ah : (which == 1) ? g_uz : g_ur;
    float acc[8];
    conv3x3_v2(g_h + n * 4096, w, oc0, sIn, sW, acc);
    int y = threadIdx.x & 7, oc = oc0 + (threadIdx.x >> 3);
    float bv = (which == 0) ? b_ah[oc] : 0.f;
    float* o = out + n * 4096 + oc * 64 + y * 8;
#pragma unroll
    for (int j = 0; j < 8; j++) o[j] = acc[j] + bv;
}

__global__ void __launch_bounds__(128) conv_share_v2(const float* __restrict__ w,
                                                     const float* __restrict__ bias,
                                                     int t0) {
    __shared__ float sIn[64 * CPAD];
    __shared__ float sW[16 * WPAD];
    int n = blockIdx.x, oc0 = blockIdx.y * 16;
    float acc[8];
    conv3x3_v2(g_wxt0 + n * 4096, w, oc0, sIn, sW, acc);
    int y = threadIdx.x & 7, oc = oc0 + (threadIdx.x >> 3);
    float bv = bias[oc];
    int e = n * 4096 + oc * 64 + y * 8;
#pragma unroll
    for (int j = 0; j < 8; j++) {
        float wxt = acc[j] + bv;
        float z, r;
        if (t0) {
            z = sigmoidf_(wxt);
        } else {
            z = sigmoidf_(wxt + g_uz[e + j]);
            r = sigmoidf_(wxt + g_ur[e + j]);
            g_rh[e + j] = r * g_h[e + j];
        }
        g_wxtb[e + j] = wxt;
        g_zb[e + j] = z;
    }
}

__global__ void __launch_bounds__(128) conv_final_v2(const float* __restrict__ w,
                                                     int t, int t0) {
    __shared__ float sIn[64 * CPAD];
    __shared__ float sW[16 * WPAD];
    int n = blockIdx.x, oc0 = blockIdx.y * 16;
    float acc[8];
    if (!t0) {
        conv3x3_v2(g_rh + n * 4096, w, oc0, sIn, sW, acc);
    } else {
#pragma unroll
        for (int j = 0; j < 8; j++) acc[j] = 0.f;
    }
    int y = threadIdx.x & 7, oc = oc0 + (threadIdx.x >> 3);
    int e = n * 4096 + oc * 64 + y * 8;
    float* hsp = g_hs + ((t * B_ + n) * K_ + oc) * 64 + y * 8;
#pragma unroll
    for (int j = 0; j < 8; j++) {
        float hh = tanhf(g_wxtb[e + j] + acc[j]);
        float z = g_zb[e + j];
        float hprev = t0 ? 0.f : g_h[e + j];
        float hn = (1.f - z) * hh + z * hprev;
        g_h[e + j] = hn;
        hsp[j] = hn;
    }
}

// ============== fused attention: stats + fc + softmax + wxt0, per b ==========
__global__ void __launch_bounds__(256) attention_kernel(const float* __restrict__ fc1,
                                                        const float* __restrict__ fc2,
                                                        const float* __restrict__ att_b,
                                                        int t0) {
    int b = blockIdx.x;
    __shared__ float s_ah[4096];
    __shared__ float s_mean[512], s_max[512];
    __shared__ float sh[64], se[512];
    int tid = threadIdx.x;
    int warp = tid >> 5, lane = tid & 31;

    if (!t0) {
        for (int i = tid; i < 4096; i += 256) s_ah[i] = g_ah[b * 4096 + i];
    }
    __syncthreads();

#pragma unroll
    for (int q = 0; q < 64; q++) {
        int p = warp * 64 + q;
        int t = p >> 6, k = p & 63;
        const float* av = g_attv + ((b * T_ + t) * K_ + k) * 64;
        float a0, a1;
        if (t0) {
            float bk = att_b[k];
            a0 = av[lane] + bk;
            a1 = av[lane + 32] + bk;
        } else {
            const float* ah = s_ah + k * 64;
            a0 = av[lane] + ah[lane];
            a1 = av[lane + 32] + ah[lane + 32];
        }
        float v0 = fmaxf(a0, 0.f), v1 = fmaxf(a1, 0.f);
        float sum = v0 + v1;
        float mx = fmaxf(v0, v1);
#pragma unroll
        for (int o = 16; o; o >>= 1) {
            sum += __shfl_xor_sync(0xffffffffu, sum, o);
            mx = fmaxf(mx, __shfl_xor_sync(0xffffffffu, mx, o));
        }
        if (lane == 0) {
            s_mean[p] = sum * (1.f / 64.f);
            s_max[p] = mx;
        }
    }
    __syncthreads();

#pragma unroll
    for (int q = 0; q < 8; q++) {
        int dd = warp * 8 + q;
        const float* src = (dd < 32) ? s_mean : s_max;
        const float* wrow = fc1 + (dd & 31) * 512;
        float sum = 0.f;
        for (int i = lane; i < 512; i += 32) sum += src[i] * wrow[i];
#pragma unroll
        for (int o = 16; o; o >>= 1) sum += __shfl_xor_sync(0xffffffffu, sum, o);
        if (lane == 0) sh[dd] = fmaxf(sum, 0.f);
    }
    __syncthreads();

#pragma unroll
    for (int rep = 0; rep < 2; rep++) {
        int o = tid + rep * 256;
        const float* w2 = fc2 + o * 32;
        float v = 0.f;
#pragma unroll
        for (int j = 0; j < 32; j++) v += w2[j] * (sh[j] + sh[j + 32]);
        se[o] = expf(tanhf(v));
    }
    __syncthreads();

    if (tid < 64) {
        float den = 0.f;
#pragma unroll
        for (int t = 0; t < T_; t++) den += se[t * 64 + tid];
        if (den == 0.f) den = 1.f;
        float inv = 1.f / den;
#pragma unroll
        for (int t = 0; t < T_; t++) se[t * 64 + tid] *= inv;
    }
    __syncthreads();

    // wxt0 = sum_t alpha[t,k] * wxpb[b,t,k,s], float4 over s
#pragma unroll
    for (int ii = 0; ii < 4; ii++) {
        int idx4 = tid + ii * 256;         // 0..1023, = (k*64+s)/4
        int k = idx4 >> 4;
        float4 a = {0.f, 0.f, 0.f, 0.f};
#pragma unroll
        for (int t = 0; t < T_; t++) {
            float al = se[t * 64 + k];
            float4 v = *(const float4*)&g_wxpb[(b * T_ + t) * 4096 + idx4 * 4];
            a.x += al * v.x; a.y += al * v.y; a.z += al * v.z; a.w += al * v.w;
        }
        *(float4*)&g_wxt0[b * 4096 + idx4 * 4] = a;
    }
}

// ---------------- VLAD GEMM (+ fused a_sum) ----------------
__global__ void __launch_bounds__(256) vlad_gemm(const float* __restrict__ centers) {
    int b = blockIdx.y;
    int d0 = blockIdx.x * 64;
    __shared__ float As[16][64];
    __shared__ float Bs[16][64];
    int tid = threadIdx.x, tx = tid & 15, ty = tid >> 4;
    float acc[4][4];
    float asacc[4] = {0.f, 0.f, 0.f, 0.f};
#pragma unroll
    for (int i = 0; i < 4; i++)
#pragma unroll
        for (int j = 0; j < 4; j++) acc[i][j] = 0.f;

    for (int ts0 = 0; ts0 < 512; ts0 += 16) {
        int t = ts0 >> 6, s0 = ts0 & 63;
        const float* hsb = g_hs + ((t * B_ + b) * K_) * 64 + s0;
        const float* xtb = g_xtT + (size_t)(b * T_ + t) * (HW_ * D_) + s0 * D_ + d0;
#pragma unroll
        for (int i = tid; i < 1024; i += 256) {
            int k = i >> 4, kk = i & 15;
            As[kk][k] = hsb[k * 64 + kk];
        }
#pragma unroll
        for (int i = tid; i < 1024; i += 256) {
            int kk = i >> 6, dd = i & 63;
            Bs[kk][dd] = xtb[kk * D_ + dd];
        }
        __syncthreads();
#pragma unroll
        for (int i = 0; i < 4; i++) asacc[i] += As[tx][ty * 4 + i];
#pragma unroll
        for (int kk = 0; kk < 16; kk++) {
            float a[4], bb[4];
#pragma unroll
            for (int i = 0; i < 4; i++) a[i] = As[kk][ty * 4 + i];
#pragma unroll
            for (int j = 0; j < 4; j++) bb[j] = Bs[kk][tx * 4 + j];
#pragma unroll
            for (int i = 0; i < 4; i++)
#pragma unroll
                for (int j = 0; j < 4; j++) acc[i][j] += a[i] * bb[j];
        }
        __syncthreads();
    }
    // reduce asacc over tx (16 lanes within half-warp)
#pragma unroll
    for (int o = 1; o < 16; o <<= 1)
#pragma unroll
        for (int i = 0; i < 4; i++)
            asacc[i] += __shfl_xor_sync(0xffffffffu, asacc[i], o);
#pragma unroll
    for (int i = 0; i < 4; i++) {
        int k = ty * 4 + i;
        float as = asacc[i];
#pragma unroll
        for (int j = 0; j < 4; j++) {
            int d = d0 + tx * 4 + j;
            g_vlad[b * (K_ * D_) + k * D_ + d] = acc[i][j] - as * centers[k * D_ + d];
        }
    }
}

// ---------------- two-level normalization ----------------
__global__ void __launch_bounds__(256) norm_kernel(float* __restrict__ out) {
    int b = blockIdx.x, tid = threadIdx.x;
    int warp = tid >> 5, lane = tid & 31;
    __shared__ float sss[64];
    __shared__ float sinv[64];
    __shared__ float sbinv;
    const float* v = g_vlad + b * (K_ * D_);
#pragma unroll
    for (int q = 0; q < 8; q++) {
        int k = warp * 8 + q;
        const float* row = v + k * D_;
        float ss = 0.f;
        for (int i = lane; i < D_; i += 32) { float x = row[i]; ss += x * x; }
#pragma unroll
        for (int o = 16; o; o >>= 1) ss += __shfl_xor_sync(0xffffffffu, ss, o);
        if (lane == 0) sss[k] = ss;
    }
    __syncthreads();
    if (tid < 64) sinv[tid] = 1.f / fmaxf(sqrtf(sss[tid]), 1e-12f);
    __syncthreads();
    if (tid == 0) {
        float tot = 0.f;
        for (int k = 0; k < 64; k++) tot += sss[k] * sinv[k] * sinv[k];
        sbinv = 1.f / fmaxf(sqrtf(tot), 1e-12f);
    }
    __syncthreads();
    float bi = sbinv;
    for (int i = tid; i < K_ * D_; i += 256)
        out[b * (K_ * D_) + i] = v[i] * sinv[i >> 9] * bi;
}

// ---------------- launcher ----------------
extern "C" void kernel_launch(void* const* d_in, const int* in_sizes, int n_in,
                              void* d_out, int out_size) {
    const float* x       = (const float*)d_in[0];
    const float* redu_w  = (const float*)d_in[1];
    const float* redu_b  = (const float*)d_in[2];
    const float* w_x     = (const float*)d_in[3];
    const float* att_x   = (const float*)d_in[4];
    const float* att_h_w = (const float*)d_in[5];
    const float* att_b   = (const float*)d_in[6];
    const float* share_w = (const float*)d_in[7];
    const float* share_b = (const float*)d_in[8];
    const float* U_r     = (const float*)d_in[9];
    const float* U_z     = (const float*)d_in[10];
    const float* U_h     = (const float*)d_in[11];
    const float* centers = (const float*)d_in[12];
    const float* fc1_w   = (const float*)d_in[13];
    const float* fc2_w   = (const float*)d_in[14];
    float* out = (float*)d_out;

    cudaFuncSetAttribute(gemm_redu_mma, cudaFuncAttributeMaxDynamicSharedMemorySize,
                         GSMEM);

    convert_w<<<(640 * CIN_ + 1023) / 1024, 1024>>>(redu_w);
    wxw_kernel<<<96, 256>>>(redu_w, redu_b, w_x);
    transpose_x<<<dim3(24, 256), 256>>>(x);
    gemm_redu_mma<<<dim3(128, 5), 256, GSMEM>>>();

    {
        float* attv_ptr = nullptr;
        cudaGetSymbolAddress((void**)&attv_ptr, g_attv);
        float* wxpb_ptr = nullptr;
        cudaGetSymbolAddress((void**)&wxpb_ptr, g_wxpb);
        conv_plain_v2<<<dim3(NT_, 4), 128>>>(wxpb_ptr, att_x, attv_ptr);
    }

    for (int t = 0; t < T_; t++) {
        if (t > 0) conv_trio_v2<<<dim3(B_, 3, 4), 128>>>(att_h_w, att_b, U_z, U_r);
        attention_kernel<<<B_, 256>>>(fc1_w, fc2_w, att_b, t == 0);
        conv_share_v2<<<dim3(B_, 4), 128>>>(share_w, share_b, t == 0);
        conv_final_v2<<<dim3(B_, 4), 128>>>(U_h, t, t == 0);
    }

    vlad_gemm<<<dim3(8, B_), 256>>>(centers);
    norm_kernel<<<B_, 256>>>(out);
}